// round 14
// baseline (speedup 1.0000x reference)
#include <cuda_runtime.h>
#include <cuda_fp16.h>
#include <math.h>
#include <stdint.h>

#define B_   64
#define SEQ  256
#define DIM  512

// ---------------- PTX helpers (generic sm_80-era, compile under compute_103) -
__device__ __forceinline__ uint32_t smem_u32(const void* p) {
    uint32_t a;
    asm("{ .reg .u64 t; cvta.to.shared.u64 t, %1; cvt.u32.u64 %0, t; }" : "=r"(a) : "l"(p));
    return a;
}
#define CP_ASYNC16(dst, src) \
    asm volatile("cp.async.cg.shared.global [%0], [%1], 16;" :: "r"(dst), "l"(src))
#define CP_COMMIT() asm volatile("cp.async.commit_group;" ::: "memory")
#define CP_WAIT(n)  asm volatile("cp.async.wait_group %0;" :: "n"(n) : "memory")
#define LDSM_X4(r0, r1, r2, r3, addr) \
    asm volatile("ldmatrix.sync.aligned.m8n8.x4.shared.b16 {%0,%1,%2,%3}, [%4];" \
        : "=r"(r0), "=r"(r1), "=r"(r2), "=r"(r3) : "r"(addr))
#define MMA16816(d, a0, a1, a2, a3, b0, b1) \
    asm volatile("mma.sync.aligned.m16n8k16.row.col.f32.f16.f16.f32 " \
        "{%0,%1,%2,%3}, {%4,%5,%6,%7}, {%8,%9}, {%0,%1,%2,%3};" \
        : "+f"((d)[0]), "+f"((d)[1]), "+f"((d)[2]), "+f"((d)[3]) \
        : "r"(a0), "r"(a1), "r"(a2), "r"(a3), "r"(b0), "r"(b1))

// ---------------- scratch (device globals; no allocations allowed) ----------
__device__ float g_msq0[B_ * SEQ];
__device__ float g_msq1[B_ * SEQ];
__device__ __align__(16) __half g_F0h[B_ * SEQ * DIM];     // MASKED fp16 F
__device__ __align__(16) __half g_F1h[B_ * SEQ * DIM];
__device__ __align__(16) __half g_Ahp [B_ * SEQ * SEQ];    // A  [i][j] fp16
__device__ __align__(16) __half g_AThp[B_ * SEQ * SEQ];    // A^T[j][i] fp16
__device__ __align__(16) __half g_Wth0[DIM * SEQ];         // W0^T [d][i]
__device__ __align__(16) __half g_Wth1[DIM * SEQ];
__device__ __align__(16) __half g_F0a[B_ * SEQ * DIM];     // fp16 Fa
__device__ __align__(16) __half g_F1a[B_ * SEQ * DIM];

// ---------------- kernel 1: pack masked F -> fp16 + masked squared norms ----
__global__ __launch_bounds__(256) void pack_fsq(
    const float* __restrict__ F0r, const float* __restrict__ F1r,
    const float* __restrict__ m0,  const float* __restrict__ m1)
{
    int warp = threadIdx.x >> 5, lane = threadIdx.x & 31;
    int row = blockIdx.x * 8 + warp;
    int which = blockIdx.y;
    const float* src = which ? F1r : F0r;
    const float* mk  = which ? m1  : m0;
    __half* dsth = which ? g_F1h  : g_F0h;
    float*  dsq  = which ? g_msq1 : g_msq0;

    float mval = mk[row];
    const float4* p4 = (const float4*)(src + (size_t)row * DIM);
    uint2* oh = (uint2*)(dsth + (size_t)row * DIM);
    float s = 0.f;
    #pragma unroll
    for (int k = 0; k < 4; ++k) {
        int idx = lane + 32 * k;
        float4 v = p4[idx];
        s += v.x * v.x + v.y * v.y + v.z * v.z + v.w * v.w;
        __half2 lo = __floats2half2_rn(v.x * mval, v.y * mval);
        __half2 hi = __floats2half2_rn(v.z * mval, v.w * mval);
        uint2 u;
        u.x = *(uint32_t*)&lo;
        u.y = *(uint32_t*)&hi;
        oh[idx] = u;
    }
    #pragma unroll
    for (int off = 16; off > 0; off >>= 1)
        s += __shfl_down_sync(0xffffffffu, s, off);
    if (lane == 0) dsq[row] = mval * s;
}

// ---------------- kernel 2: transpose W -> Wt fp16 --------------------------
__global__ __launch_bounds__(1024) void pack_w(
    const float* __restrict__ W0, const float* __restrict__ W1)
{
    __shared__ float tile[32][33];
    int which = blockIdx.z;
    const float* W = which ? W1 : W0;
    __half* Wth = which ? g_Wth1 : g_Wth0;
    int d0 = blockIdx.x * 32, i0 = blockIdx.y * 32;
    int tx = threadIdx.x, ty = threadIdx.y;
    tile[ty][tx] = W[(size_t)(i0 + ty) * DIM + d0 + tx];
    __syncthreads();
    Wth[(size_t)(d0 + ty) * SEQ + i0 + tx] = __float2half_rn(tile[tx][ty]);
}

// ---------------- pipelined GEMM core (used by cross) ------------------------
// A tile fixed 128 rows; B tile BROWS rows; 128B rows, K-chunk 64.
// Swizzle: 16B chunk c of row r stored at chunk (c ^ (r&7)).
template <int BROWS>
__device__ __forceinline__ void load_chunk64(
    const __half* __restrict__ gA, const __half* __restrict__ gB,
    int strideA, int strideB, uint32_t sA, uint32_t sB, int tid)
{
    #pragma unroll
    for (int it = 0; it < 4; ++it) {
        int u = tid + it * 256;
        int row = u >> 3, c = u & 7;
        int sw = c ^ (row & 7);
        CP_ASYNC16(sA + row * 128 + sw * 16, gA + (size_t)row * strideA + c * 8);
    }
    #pragma unroll
    for (int it = 0; it < BROWS / 32; ++it) {
        int u = tid + it * 256;
        int row = u >> 3, c = u & 7;
        int sw = c ^ (row & 7);
        CP_ASYNC16(sB + row * 128 + sw * 16, gB + (size_t)row * strideB + c * 8);
    }
}

template <int MT>
__device__ __forceinline__ void load_frags_kk(
    uint32_t sA, uint32_t sB, int lane, int wm, int wn, int kk,
    uint32_t a[MT][4], uint32_t bfr[2][4])
{
    #pragma unroll
    for (int mt = 0; mt < MT; ++mt) {
        int row = wm + mt * 16 + (lane & 15);
        int ch = (kk * 2 + (lane >> 4)) ^ (row & 7);
        LDSM_X4(a[mt][0], a[mt][1], a[mt][2], a[mt][3], sA + row * 128 + ch * 16);
    }
    #pragma unroll
    for (int g = 0; g < 2; ++g) {
        int row = wn + g * 16 + (lane & 15);
        int ch = (kk * 2 + (lane >> 4)) ^ (row & 7);
        LDSM_X4(bfr[g][0], bfr[g][1], bfr[g][2], bfr[g][3], sB + row * 128 + ch * 16);
    }
}

template <int MT>
__device__ __forceinline__ void mma_frags_kk(
    uint32_t a[MT][4], uint32_t bfr[2][4], float acc[MT][4][4])
{
    #pragma unroll
    for (int mt = 0; mt < MT; ++mt)
        #pragma unroll
        for (int nt = 0; nt < 4; ++nt) {
            uint32_t b01 = bfr[nt >> 1][nt & 1];
            uint32_t b23 = bfr[nt >> 1][(nt & 1) + 2];
            MMA16816(acc[mt][nt], a[mt][0], a[mt][1], a[mt][2], a[mt][3], b01, b23);
        }
}

template <int NC, int MT, int BROWS>
__device__ __forceinline__ void gemm_main3(
    const __half* __restrict__ gA, const __half* __restrict__ gB,
    int strideA, int strideB, uint32_t base,
    int tid, int lane, int wm, int wn, float acc[MT][4][4])
{
    const uint32_t STG = 16384 + BROWS * 128;
    load_chunk64<BROWS>(gA,      gB,      strideA, strideB, base,       base + 16384,       tid); CP_COMMIT();
    load_chunk64<BROWS>(gA + 64, gB + 64, strideA, strideB, base + STG, base + STG + 16384, tid); CP_COMMIT();
    int cur = 0, nxt = 2;
    #pragma unroll 1
    for (int c = 0; c < NC; ++c) {
        if (c + 2 < NC) CP_WAIT(1); else CP_WAIT(0);
        __syncthreads();
        uint32_t sA = base + cur * STG, sB = sA + 16384;
        uint32_t a0[MT][4], b0[2][4], a1[MT][4], b1[2][4];
        load_frags_kk<MT>(sA, sB, lane, wm, wn, 0, a0, b0);
        if (c + 2 < NC) {
            uint32_t sa = base + nxt * STG;
            load_chunk64<BROWS>(gA + (c + 2) * 64, gB + (c + 2) * 64, strideA, strideB,
                                sa, sa + 16384, tid);
            CP_COMMIT();
            nxt = (nxt == 2) ? 0 : nxt + 1;
        }
        load_frags_kk<MT>(sA, sB, lane, wm, wn, 1, a1, b1);
        mma_frags_kk<MT>(a0, b0, acc);
        load_frags_kk<MT>(sA, sB, lane, wm, wn, 2, a0, b0);
        mma_frags_kk<MT>(a1, b1, acc);
        load_frags_kk<MT>(sA, sB, lane, wm, wn, 3, a1, b1);
        mma_frags_kk<MT>(a0, b0, acc);
        mma_frags_kk<MT>(a1, b1, acc);
        cur = (cur == 2) ? 0 : cur + 1;
    }
}

// ---------------- kernel 3: cross GEMM + A epilogue + smem transpose --------
// tile 128x128 (8 warps of 64x32); 3-stage x 32KB = 96KB dyn smem, 2 CTAs/SM
#define TP_STRIDE 136
#define CROSS_SMEM (3 * 32768)

__global__ __launch_bounds__(256, 2) void cross_mma()
{
    extern __shared__ __align__(1024) char dsm[];
    uint32_t sb = smem_u32(dsm);

    int tid = threadIdx.x, wid = tid >> 5, lane = tid & 31;
    int wm = (wid & 1) * 64, wn = (wid >> 1) * 32;
    int i0 = blockIdx.x * 128, j0 = blockIdx.y * 128, b = blockIdx.z;

    const __half* gA = g_F0h + ((size_t)b * SEQ + i0) * DIM;
    const __half* gB = g_F1h + ((size_t)b * SEQ + j0) * DIM;

    float acc[4][4][4] = {};
    gemm_main3<8, 4, 128>(gA, gB, DIM, DIM, sb, tid, lane, wm, wn, acc);

    __syncthreads();   // smem about to be reused as transpose buffer

    int bs = b * SEQ;
    float sj[8];
    #pragma unroll
    for (int q = 0; q < 8; ++q) {
        int j = j0 + wn + (q >> 1) * 8 + (lane & 3) * 2 + (q & 1);
        sj[q] = g_msq1[bs + j];
    }
    #pragma unroll
    for (int mt = 0; mt < 4; ++mt)
        #pragma unroll
        for (int h = 0; h < 2; ++h) {
            int il = wm + mt * 16 + h * 8 + (lane >> 2);   // local i (0..127)
            int i = i0 + il;
            float si = g_msq0[bs + i];
            #pragma unroll
            for (int nt = 0; nt < 4; ++nt) {
                int jl = wn + nt * 8 + (lane & 3) * 2;     // local j
                float c0 = acc[mt][nt][h * 2 + 0];
                float c1 = acc[mt][nt][h * 2 + 1];
                float d20 = fmaxf(si + sj[nt * 2 + 0] - 2.f * c0, 0.f);
                float d21 = fmaxf(si + sj[nt * 2 + 1] - 2.f * c1, 0.f);
                float A0 = 1.f / (1.f + sqrtf(d20));
                float A1 = 1.f / (1.f + sqrtf(d21));
                __half h0 = __float2half_rn(A0), h1 = __float2half_rn(A1);
                uint32_t pk = (uint32_t)__half_as_ushort(h0)
                            | ((uint32_t)__half_as_ushort(h1) << 16);
                *(uint32_t*)&g_Ahp[((size_t)bs + i) * SEQ + j0 + jl] = pk;
                __half* tp = (__half*)dsm;
                tp[(size_t)jl * TP_STRIDE + il]       = h0;
                tp[(size_t)(jl + 1) * TP_STRIDE + il] = h1;
            }
        }
    __syncthreads();
    const __half* tp = (const __half*)dsm;
    #pragma unroll
    for (int k = 0; k < 8; ++k) {
        int idx = tid + k * 256;
        int j = idx >> 4, seg = idx & 15;
        uint4 v = *(const uint4*)(tp + (size_t)j * TP_STRIDE + seg * 8);
        *(uint4*)&g_AThp[((size_t)bs + j0 + j) * SEQ + i0 + seg * 8] = v;
    }
}

// ---------------- kernel 4: A@W GEMM -> Fa fp16  (ONE-SHOT, no mainloop) ----
// tile 128x64; full K=256 resident: A 64KB + B 32KB = 96KB smem; 2 CTAs/SM.
// Rows are 512B (256 halfs, 32x16B chunks). Swizzle: chunk c of row r at
// (c & 24) | ((c ^ r) & 7)  -- permutes within each 128B quarter.
#define AW_SMEM (96 * 1024)

__device__ __forceinline__ void aw_ldfr(
    uint32_t sA, uint32_t sB, int lane, int wm, int wn, int kk,
    uint32_t a[2][4], uint32_t bfr[2][4])
{
    int chb = kk * 2 + (lane >> 4);
    #pragma unroll
    for (int mt = 0; mt < 2; ++mt) {
        int row = wm + mt * 16 + (lane & 15);
        int ch = (chb & 24) | ((chb ^ row) & 7);
        LDSM_X4(a[mt][0], a[mt][1], a[mt][2], a[mt][3], sA + row * 512 + ch * 16);
    }
    #pragma unroll
    for (int g = 0; g < 2; ++g) {
        int row = wn + g * 16 + (lane & 15);
        int ch = (chb & 24) | ((chb ^ row) & 7);
        LDSM_X4(bfr[g][0], bfr[g][1], bfr[g][2], bfr[g][3], sB + row * 512 + ch * 16);
    }
}

__global__ __launch_bounds__(256, 2) void aw_mma()
{
    extern __shared__ __align__(1024) char dsm[];
    uint32_t sb = smem_u32(dsm);
    uint32_t sA = sb, sB = sb + 65536;

    int tid = threadIdx.x, wid = tid >> 5, lane = tid & 31;
    int wm = (wid & 3) * 32, wn = (wid >> 2) * 32;
    int n0 = blockIdx.x * 64, mr0 = blockIdx.y * 128;
    int z = blockIdx.z, b = z >> 1, var = z & 1;

    const __half* gA = (var ? g_Ahp : g_AThp) + ((size_t)b * SEQ + mr0) * SEQ;
    const __half* gB = (var ? g_Wth1 : g_Wth0) + (size_t)n0 * SEQ;

    // one-shot load of full K: A 128x256, B 64x256
    #pragma unroll
    for (int it = 0; it < 16; ++it) {
        int u = tid + it * 256;
        int row = u >> 5, c = u & 31;
        int sw = (c & 24) | ((c ^ row) & 7);
        CP_ASYNC16(sA + row * 512 + sw * 16, gA + (size_t)row * SEQ + c * 8);
    }
    #pragma unroll
    for (int it = 0; it < 8; ++it) {
        int u = tid + it * 256;
        int row = u >> 5, c = u & 31;
        int sw = (c & 24) | ((c ^ row) & 7);
        CP_ASYNC16(sB + row * 512 + sw * 16, gB + (size_t)row * SEQ + c * 8);
    }
    CP_COMMIT();
    CP_WAIT(0);
    __syncthreads();               // the ONLY barrier

    float acc[2][4][4] = {};
    uint32_t a0[2][4], b0[2][4], a1[2][4], b1[2][4];
    aw_ldfr(sA, sB, lane, wm, wn, 0, a0, b0);
    #pragma unroll
    for (int kk = 0; kk < 16; ++kk) {
        if (kk + 1 < 16) {
            if (kk & 1) aw_ldfr(sA, sB, lane, wm, wn, kk + 1, a0, b0);
            else        aw_ldfr(sA, sB, lane, wm, wn, kk + 1, a1, b1);
        }
        if (kk & 1) mma_frags_kk<2>(a1, b1, acc);
        else        mma_frags_kk<2>(a0, b0, acc);
    }

    __half* outp = (var ? g_F1a : g_F0a) + (size_t)b * SEQ * DIM;
    #pragma unroll
    for (int mt = 0; mt < 2; ++mt)
        #pragma unroll
        for (int h = 0; h < 2; ++h) {
            int r = mr0 + wm + mt * 16 + h * 8 + (lane >> 2);
            #pragma unroll
            for (int nt = 0; nt < 4; ++nt) {
                int d = n0 + wn + nt * 8 + (lane & 3) * 2;
                __half2 v = __floats2half2_rn(acc[mt][nt][h * 2], acc[mt][nt][h * 2 + 1]);
                *(__half2*)&outp[(size_t)r * DIM + d] = v;
            }
        }
}

// ---------------- kernel 5: fused conv(3x1) + tanh + avgpool(3x1) -----------
__device__ __forceinline__ void loadq2(
    const __half2* __restrict__ Fb, const __half2* __restrict__ Gb,
    int h0, float2* f, float2* g)
{
    #pragma unroll
    for (int q = 0; q < 4; ++q) {
        int h = h0 + q;
        if ((unsigned)h < (unsigned)SEQ) {
            f[q] = __half22float2(Fb[(size_t)h * (DIM / 2)]);
            g[q] = __half22float2(Gb[(size_t)h * (DIM / 2)]);
        } else { f[q] = make_float2(0.f, 0.f); g[q] = make_float2(0.f, 0.f); }
    }
}

__global__ __launch_bounds__(256) void conv_kernel(
    const float* __restrict__ conv_w, const float* __restrict__ conv_b,
    float* __restrict__ out)
{
    int dp = threadIdx.x;
    int s0 = blockIdx.x * 32;
    int b  = blockIdx.y;
    int br = blockIdx.z;

    const __half* Fh = br ? g_F1h : g_F0h;
    const __half* Fa = br ? g_F1a : g_F0a;

    float w00 = conv_w[0], w01 = conv_w[1], w02 = conv_w[2];
    float w10 = conv_w[3], w11 = conv_w[4], w12 = conv_w[5];
    float bias = conv_b[0];

    const __half2* Fb = (const __half2*)(Fh + (size_t)b * SEQ * DIM) + dp;
    const __half2* Gb = (const __half2*)(Fa + (size_t)b * SEQ * DIM) + dp;
    float* ob = out + (size_t)br * B_ * SEQ * DIM + (size_t)b * SEQ * DIM + dp * 2;

    float2 cf[4], cg[4], n1f[4], n1g[4], n2f[4], n2g[4];
    loadq2(Fb, Gb, s0 - 2, cf,  cg);
    loadq2(Fb, Gb, s0 + 2, n1f, n1g);

    float2 f0 = {0.f,0.f}, f1 = {0.f,0.f}, g0 = {0.f,0.f}, g1 = {0.f,0.f};
    float2 t0 = {0.f,0.f}, t1 = {0.f,0.f};

    #pragma unroll 1
    for (int ch = 0; ch < 9; ++ch) {
        int hb = s0 - 2 + ch * 4;
        if (ch + 2 < 9) loadq2(Fb, Gb, hb + 8, n2f, n2g);
        #pragma unroll
        for (int q = 0; q < 4; ++q) {
            int h = hb + q;
            float2 f2 = cf[q], g2 = cg[q];
            float yx = w00 * f0.x + w01 * f1.x + w02 * f2.x
                     + w10 * g0.x + w11 * g1.x + w12 * g2.x + bias;
            float yy = w00 * f0.y + w01 * f1.y + w02 * f2.y
                     + w10 * g0.y + w11 * g1.y + w12 * g2.y + bias;
            float2 t2 = make_float2(tanhf(yx), tanhf(yy));
            if (h >= s0 + 2 && h < s0 + 34) {
                float2 o = make_float2((t0.x + t1.x + t2.x) * (1.f / 3.f),
                                       (t0.y + t1.y + t2.y) * (1.f / 3.f));
                __stcs((float2*)&ob[(size_t)(h - 2) * DIM], o);
            }
            t0 = t1; t1 = t2;
            f0 = f1; f1 = f2;
            g0 = g1; g1 = g2;
        }
        #pragma unroll
        for (int q = 0; q < 4; ++q) {
            cf[q] = n1f[q]; cg[q] = n1g[q];
            n1f[q] = n2f[q]; n1g[q] = n2g[q];
        }
    }
}

// ---------------- launch ----------------------------------------------------
extern "C" void kernel_launch(void* const* d_in, const int* in_sizes, int n_in,
                              void* d_out, int out_size)
{
    const float* F0r    = (const float*)d_in[0];
    const float* F1r    = (const float*)d_in[1];
    const float* m0     = (const float*)d_in[2];
    const float* m1     = (const float*)d_in[3];
    const float* W0     = (const float*)d_in[4];
    const float* W1     = (const float*)d_in[5];
    const float* conv_w = (const float*)d_in[6];
    const float* conv_b = (const float*)d_in[7];
    float* out = (float*)d_out;

    cudaFuncSetAttribute(cross_mma, cudaFuncAttributeMaxDynamicSharedMemorySize, CROSS_SMEM);
    cudaFuncSetAttribute(aw_mma,    cudaFuncAttributeMaxDynamicSharedMemorySize, AW_SMEM);

    pack_fsq <<<dim3(B_ * SEQ / 8, 2), 256>>>(F0r, F1r, m0, m1);
    pack_w   <<<dim3(16, 8, 2), dim3(32, 32)>>>(W0, W1);
    cross_mma<<<dim3(2, 2, B_), 256, CROSS_SMEM>>>();
    aw_mma   <<<dim3(8, 2, B_ * 2), 256, AW_SMEM>>>();
    conv_kernel<<<dim3(SEQ / 32, B_, 2), 256>>>(conv_w, conv_b, out);
}

// round 15
// speedup vs baseline: 1.4463x; 1.4463x over previous
#include <cuda_runtime.h>
#include <cuda_fp16.h>
#include <math.h>
#include <stdint.h>

#define B_   64
#define SEQ  256
#define DIM  512

// ---------------- PTX helpers (generic sm_80-era, compile under compute_103) -
__device__ __forceinline__ uint32_t smem_u32(const void* p) {
    uint32_t a;
    asm("{ .reg .u64 t; cvta.to.shared.u64 t, %1; cvt.u32.u64 %0, t; }" : "=r"(a) : "l"(p));
    return a;
}
#define CP_ASYNC16(dst, src) \
    asm volatile("cp.async.cg.shared.global [%0], [%1], 16;" :: "r"(dst), "l"(src))
#define CP_COMMIT() asm volatile("cp.async.commit_group;" ::: "memory")
#define CP_WAIT(n)  asm volatile("cp.async.wait_group %0;" :: "n"(n) : "memory")
#define LDSM_X4(r0, r1, r2, r3, addr) \
    asm volatile("ldmatrix.sync.aligned.m8n8.x4.shared.b16 {%0,%1,%2,%3}, [%4];" \
        : "=r"(r0), "=r"(r1), "=r"(r2), "=r"(r3) : "r"(addr))
#define MMA16816(d, a0, a1, a2, a3, b0, b1) \
    asm volatile("mma.sync.aligned.m16n8k16.row.col.f32.f16.f16.f32 " \
        "{%0,%1,%2,%3}, {%4,%5,%6,%7}, {%8,%9}, {%0,%1,%2,%3};" \
        : "+f"((d)[0]), "+f"((d)[1]), "+f"((d)[2]), "+f"((d)[3]) \
        : "r"(a0), "r"(a1), "r"(a2), "r"(a3), "r"(b0), "r"(b1))

// ---------------- scratch (device globals; no allocations allowed) ----------
__device__ float g_msq0[B_ * SEQ];
__device__ float g_msq1[B_ * SEQ];
__device__ __align__(16) __half g_F0h[B_ * SEQ * DIM];     // MASKED fp16 F
__device__ __align__(16) __half g_F1h[B_ * SEQ * DIM];
__device__ __align__(16) __half g_Ahp [B_ * SEQ * SEQ];    // A  [i][j] fp16
__device__ __align__(16) __half g_AThp[B_ * SEQ * SEQ];    // A^T[j][i] fp16
__device__ __align__(16) __half g_Wth0[DIM * SEQ];         // W0^T [d][i]
__device__ __align__(16) __half g_Wth1[DIM * SEQ];
__device__ __align__(16) __half g_F0a[B_ * SEQ * DIM];     // fp16 Fa
__device__ __align__(16) __half g_F1a[B_ * SEQ * DIM];

// ---------------- kernel 1: pack masked F -> fp16 + masked squared norms ----
__global__ __launch_bounds__(256) void pack_fsq(
    const float* __restrict__ F0r, const float* __restrict__ F1r,
    const float* __restrict__ m0,  const float* __restrict__ m1)
{
    int warp = threadIdx.x >> 5, lane = threadIdx.x & 31;
    int row = blockIdx.x * 8 + warp;
    int which = blockIdx.y;
    const float* src = which ? F1r : F0r;
    const float* mk  = which ? m1  : m0;
    __half* dsth = which ? g_F1h  : g_F0h;
    float*  dsq  = which ? g_msq1 : g_msq0;

    float mval = mk[row];
    const float4* p4 = (const float4*)(src + (size_t)row * DIM);
    uint2* oh = (uint2*)(dsth + (size_t)row * DIM);
    float s = 0.f;
    #pragma unroll
    for (int k = 0; k < 4; ++k) {
        int idx = lane + 32 * k;
        float4 v = p4[idx];
        s += v.x * v.x + v.y * v.y + v.z * v.z + v.w * v.w;
        __half2 lo = __floats2half2_rn(v.x * mval, v.y * mval);
        __half2 hi = __floats2half2_rn(v.z * mval, v.w * mval);
        uint2 u;
        u.x = *(uint32_t*)&lo;
        u.y = *(uint32_t*)&hi;
        oh[idx] = u;
    }
    #pragma unroll
    for (int off = 16; off > 0; off >>= 1)
        s += __shfl_down_sync(0xffffffffu, s, off);
    if (lane == 0) dsq[row] = mval * s;
}

// ---------------- kernel 2: transpose W -> Wt fp16 --------------------------
__global__ __launch_bounds__(1024) void pack_w(
    const float* __restrict__ W0, const float* __restrict__ W1)
{
    __shared__ float tile[32][33];
    int which = blockIdx.z;
    const float* W = which ? W1 : W0;
    __half* Wth = which ? g_Wth1 : g_Wth0;
    int d0 = blockIdx.x * 32, i0 = blockIdx.y * 32;
    int tx = threadIdx.x, ty = threadIdx.y;
    tile[ty][tx] = W[(size_t)(i0 + ty) * DIM + d0 + tx];
    __syncthreads();
    Wth[(size_t)(d0 + ty) * SEQ + i0 + tx] = __float2half_rn(tile[tx][ty]);
}

// ---------------- shared GEMM core (3-stage, K-chunk 64, kk-pipelined) ------
// A tile fixed 128 rows; B tile BROWS rows (64 or 128); 128B rows.
// Swizzle: 16B chunk c of row r stored at chunk (c ^ (r&7)).
template <int BROWS>
__device__ __forceinline__ void load_chunk64(
    const __half* __restrict__ gA, const __half* __restrict__ gB,
    int strideA, int strideB, uint32_t sA, uint32_t sB, int tid)
{
    #pragma unroll
    for (int it = 0; it < 4; ++it) {
        int u = tid + it * 256;
        int row = u >> 3, c = u & 7;
        int sw = c ^ (row & 7);
        CP_ASYNC16(sA + row * 128 + sw * 16, gA + (size_t)row * strideA + c * 8);
    }
    #pragma unroll
    for (int it = 0; it < BROWS / 32; ++it) {
        int u = tid + it * 256;
        int row = u >> 3, c = u & 7;
        int sw = c ^ (row & 7);
        CP_ASYNC16(sB + row * 128 + sw * 16, gB + (size_t)row * strideB + c * 8);
    }
}

template <int MT>
__device__ __forceinline__ void load_frags_kk(
    uint32_t sA, uint32_t sB, int lane, int wm, int wn, int kk,
    uint32_t a[MT][4], uint32_t bfr[2][4])
{
    #pragma unroll
    for (int mt = 0; mt < MT; ++mt) {
        int row = wm + mt * 16 + (lane & 15);
        int ch = (kk * 2 + (lane >> 4)) ^ (row & 7);
        LDSM_X4(a[mt][0], a[mt][1], a[mt][2], a[mt][3], sA + row * 128 + ch * 16);
    }
    #pragma unroll
    for (int g = 0; g < 2; ++g) {
        int row = wn + g * 16 + (lane & 15);
        int ch = (kk * 2 + (lane >> 4)) ^ (row & 7);
        LDSM_X4(bfr[g][0], bfr[g][1], bfr[g][2], bfr[g][3], sB + row * 128 + ch * 16);
    }
}

template <int MT>
__device__ __forceinline__ void mma_frags_kk(
    uint32_t a[MT][4], uint32_t bfr[2][4], float acc[MT][4][4])
{
    #pragma unroll
    for (int mt = 0; mt < MT; ++mt)
        #pragma unroll
        for (int nt = 0; nt < 4; ++nt) {
            uint32_t b01 = bfr[nt >> 1][nt & 1];
            uint32_t b23 = bfr[nt >> 1][(nt & 1) + 2];
            MMA16816(acc[mt][nt], a[mt][0], a[mt][1], a[mt][2], a[mt][3], b01, b23);
        }
}

// NC = number of 64-wide K-chunks; MT = warp M-subtiles; BROWS = B tile rows
template <int NC, int MT, int BROWS>
__device__ __forceinline__ void gemm_main3(
    const __half* __restrict__ gA, const __half* __restrict__ gB,
    int strideA, int strideB, uint32_t base,
    int tid, int lane, int wm, int wn, float acc[MT][4][4])
{
    const uint32_t STG = 16384 + BROWS * 128;
    load_chunk64<BROWS>(gA,      gB,      strideA, strideB, base,       base + 16384,       tid); CP_COMMIT();
    load_chunk64<BROWS>(gA + 64, gB + 64, strideA, strideB, base + STG, base + STG + 16384, tid); CP_COMMIT();
    int cur = 0, nxt = 2;
    #pragma unroll 1
    for (int c = 0; c < NC; ++c) {
        if (c + 2 < NC) CP_WAIT(1); else CP_WAIT(0);
        __syncthreads();
        uint32_t sA = base + cur * STG, sB = sA + 16384;
        uint32_t a0[MT][4], b0[2][4], a1[MT][4], b1[2][4];
        load_frags_kk<MT>(sA, sB, lane, wm, wn, 0, a0, b0);
        if (c + 2 < NC) {                      // issue next-chunk async loads
            uint32_t sa = base + nxt * STG;
            load_chunk64<BROWS>(gA + (c + 2) * 64, gB + (c + 2) * 64, strideA, strideB,
                                sa, sa + 16384, tid);
            CP_COMMIT();
            nxt = (nxt == 2) ? 0 : nxt + 1;
        }
        load_frags_kk<MT>(sA, sB, lane, wm, wn, 1, a1, b1);
        mma_frags_kk<MT>(a0, b0, acc);
        load_frags_kk<MT>(sA, sB, lane, wm, wn, 2, a0, b0);
        mma_frags_kk<MT>(a1, b1, acc);
        load_frags_kk<MT>(sA, sB, lane, wm, wn, 3, a1, b1);
        mma_frags_kk<MT>(a0, b0, acc);
        mma_frags_kk<MT>(a1, b1, acc);
        cur = (cur == 2) ? 0 : cur + 1;
    }
}

// ---------------- kernel 3: cross GEMM + A epilogue + smem transpose --------
// tile 128x128 (8 warps of 64x32); 3-stage x 32KB = 96KB dyn smem, 2 CTAs/SM
// transpose buffer: 128 rows (j) x 136 halfs (i + 8 pad) = 34816 B (reuses smem)
#define TP_STRIDE 136
#define CROSS_SMEM (3 * 32768)

__global__ __launch_bounds__(256, 2) void cross_mma()
{
    extern __shared__ __align__(1024) char dsm[];
    uint32_t sb = smem_u32(dsm);

    int tid = threadIdx.x, wid = tid >> 5, lane = tid & 31;
    int wm = (wid & 1) * 64, wn = (wid >> 1) * 32;
    int i0 = blockIdx.x * 128, j0 = blockIdx.y * 128, b = blockIdx.z;

    const __half* gA = g_F0h + ((size_t)b * SEQ + i0) * DIM;
    const __half* gB = g_F1h + ((size_t)b * SEQ + j0) * DIM;

    float acc[4][4][4] = {};
    gemm_main3<8, 4, 128>(gA, gB, DIM, DIM, sb, tid, lane, wm, wn, acc);

    __syncthreads();   // smem about to be reused as transpose buffer

    int bs = b * SEQ;
    float sj[8];
    #pragma unroll
    for (int q = 0; q < 8; ++q) {
        int j = j0 + wn + (q >> 1) * 8 + (lane & 3) * 2 + (q & 1);
        sj[q] = g_msq1[bs + j];
    }
    #pragma unroll
    for (int mt = 0; mt < 4; ++mt)
        #pragma unroll
        for (int h = 0; h < 2; ++h) {
            int il = wm + mt * 16 + h * 8 + (lane >> 2);   // local i (0..127)
            int i = i0 + il;
            float si = g_msq0[bs + i];
            #pragma unroll
            for (int nt = 0; nt < 4; ++nt) {
                int jl = wn + nt * 8 + (lane & 3) * 2;     // local j
                float c0 = acc[mt][nt][h * 2 + 0];
                float c1 = acc[mt][nt][h * 2 + 1];
                float d20 = fmaxf(si + sj[nt * 2 + 0] - 2.f * c0, 0.f);
                float d21 = fmaxf(si + sj[nt * 2 + 1] - 2.f * c1, 0.f);
                float A0 = 1.f / (1.f + sqrtf(d20));
                float A1 = 1.f / (1.f + sqrtf(d21));
                __half h0 = __float2half_rn(A0), h1 = __float2half_rn(A1);
                uint32_t pk = (uint32_t)__half_as_ushort(h0)
                            | ((uint32_t)__half_as_ushort(h1) << 16);
                // row-major A: direct global store
                *(uint32_t*)&g_Ahp[((size_t)bs + i) * SEQ + j0 + jl] = pk;
                // transposed into smem [j][i]
                __half* tp = (__half*)dsm;
                tp[(size_t)jl * TP_STRIDE + il]       = h0;
                tp[(size_t)(jl + 1) * TP_STRIDE + il] = h1;
            }
        }
    __syncthreads();
    // coalesced AT writes: 128 rows x 16 uint4
    const __half* tp = (const __half*)dsm;
    #pragma unroll
    for (int k = 0; k < 8; ++k) {
        int idx = tid + k * 256;
        int j = idx >> 4, seg = idx & 15;
        uint4 v = *(const uint4*)(tp + (size_t)j * TP_STRIDE + seg * 8);
        *(uint4*)&g_AThp[((size_t)bs + j0 + j) * SEQ + i0 + seg * 8] = v;
    }
}

// ---------------- kernel 4: A@W GEMM -> Fa fp16 -----------------------------
// tile 128x64 (8 warps of 32x32); 3-stage x 24KB = 72KB dyn smem, 3 CTAs/SM
#define AW_SMEM (3 * 24576)

__global__ __launch_bounds__(256, 3) void aw_mma()
{
    extern __shared__ __align__(1024) char dsm[];
    uint32_t sb = smem_u32(dsm);

    int tid = threadIdx.x, wid = tid >> 5, lane = tid & 31;
    int wm = (wid & 3) * 32, wn = (wid >> 2) * 32;
    int n0 = blockIdx.x * 64, mr0 = blockIdx.y * 128;
    int z = blockIdx.z, b = z >> 1, var = z & 1;

    const __half* gA = (var ? g_Ahp : g_AThp) + ((size_t)b * SEQ + mr0) * SEQ;
    const __half* gB = (var ? g_Wth1 : g_Wth0) + (size_t)n0 * SEQ;

    float acc[2][4][4] = {};
    gemm_main3<4, 2, 64>(gA, gB, SEQ, SEQ, sb, tid, lane, wm, wn, acc);

    __half* outp = (var ? g_F1a : g_F0a) + (size_t)b * SEQ * DIM;
    #pragma unroll
    for (int mt = 0; mt < 2; ++mt)
        #pragma unroll
        for (int h = 0; h < 2; ++h) {
            int r = mr0 + wm + mt * 16 + h * 8 + (lane >> 2);
            #pragma unroll
            for (int nt = 0; nt < 4; ++nt) {
                int d = n0 + wn + nt * 8 + (lane & 3) * 2;
                __half2 v = __floats2half2_rn(acc[mt][nt][h * 2], acc[mt][nt][h * 2 + 1]);
                *(__half2*)&outp[(size_t)r * DIM + d] = v;
            }
        }
}

// ---------------- kernel 5: fused conv(3x1) + tanh + avgpool(3x1) -----------
// 256 threads, each handles 2 adjacent d via half2; 32-row s-chunks;
// depth-2 chunk prefetch; __ldcs streaming loads (read-once data),
// __stcs streaming stores for the write-only fp32 output.
__device__ __forceinline__ void loadq2(
    const __half2* __restrict__ Fb, const __half2* __restrict__ Gb,
    int h0, float2* f, float2* g)
{
    #pragma unroll
    for (int q = 0; q < 4; ++q) {
        int h = h0 + q;
        if ((unsigned)h < (unsigned)SEQ) {
            f[q] = __half22float2(__ldcs(Fb + (size_t)h * (DIM / 2)));
            g[q] = __half22float2(__ldcs(Gb + (size_t)h * (DIM / 2)));
        } else { f[q] = make_float2(0.f, 0.f); g[q] = make_float2(0.f, 0.f); }
    }
}

__global__ __launch_bounds__(256) void conv_kernel(
    const float* __restrict__ conv_w, const float* __restrict__ conv_b,
    float* __restrict__ out)
{
    int dp = threadIdx.x;            // 0..255 -> d pair
    int s0 = blockIdx.x * 32;
    int b  = blockIdx.y;
    int br = blockIdx.z;

    const __half* Fh = br ? g_F1h : g_F0h;   // masked fp16 F
    const __half* Fa = br ? g_F1a : g_F0a;

    float w00 = conv_w[0], w01 = conv_w[1], w02 = conv_w[2];
    float w10 = conv_w[3], w11 = conv_w[4], w12 = conv_w[5];
    float bias = conv_b[0];

    const __half2* Fb = (const __half2*)(Fh + (size_t)b * SEQ * DIM) + dp;
    const __half2* Gb = (const __half2*)(Fa + (size_t)b * SEQ * DIM) + dp;
    float* ob = out + (size_t)br * B_ * SEQ * DIM + (size_t)b * SEQ * DIM + dp * 2;

    // 3 rotating 4-row buffers (depth-2 prefetch), explicit register rotation
    float2 cf[4], cg[4], n1f[4], n1g[4], n2f[4], n2g[4];
    loadq2(Fb, Gb, s0 - 2, cf,  cg);
    loadq2(Fb, Gb, s0 + 2, n1f, n1g);

    float2 f0 = {0.f,0.f}, f1 = {0.f,0.f}, g0 = {0.f,0.f}, g1 = {0.f,0.f};
    float2 t0 = {0.f,0.f}, t1 = {0.f,0.f};

    #pragma unroll 1
    for (int ch = 0; ch < 9; ++ch) {
        int hb = s0 - 2 + ch * 4;
        if (ch + 2 < 9) loadq2(Fb, Gb, hb + 8, n2f, n2g);
        #pragma unroll
        for (int q = 0; q < 4; ++q) {
            int h = hb + q;
            float2 f2 = cf[q], g2 = cg[q];
            float yx = w00 * f0.x + w01 * f1.x + w02 * f2.x
                     + w10 * g0.x + w11 * g1.x + w12 * g2.x + bias;
            float yy = w00 * f0.y + w01 * f1.y + w02 * f2.y
                     + w10 * g0.y + w11 * g1.y + w12 * g2.y + bias;
            float2 t2 = make_float2(tanhf(yx), tanhf(yy));
            if (h >= s0 + 2 && h < s0 + 34) {
                float2 o = make_float2((t0.x + t1.x + t2.x) * (1.f / 3.f),
                                       (t0.y + t1.y + t2.y) * (1.f / 3.f));
                __stcs((float2*)&ob[(size_t)(h - 2) * DIM], o);
            }
            t0 = t1; t1 = t2;
            f0 = f1; f1 = f2;
            g0 = g1; g1 = g2;
        }
        #pragma unroll
        for (int q = 0; q < 4; ++q) {
            cf[q] = n1f[q]; cg[q] = n1g[q];
            n1f[q] = n2f[q]; n1g[q] = n2g[q];
        }
    }
}

// ---------------- launch ----------------------------------------------------
extern "C" void kernel_launch(void* const* d_in, const int* in_sizes, int n_in,
                              void* d_out, int out_size)
{
    const float* F0r    = (const float*)d_in[0];
    const float* F1r    = (const float*)d_in[1];
    const float* m0     = (const float*)d_in[2];
    const float* m1     = (const float*)d_in[3];
    const float* W0     = (const float*)d_in[4];
    const float* W1     = (const float*)d_in[5];
    const float* conv_w = (const float*)d_in[6];
    const float* conv_b = (const float*)d_in[7];
    float* out = (float*)d_out;

    cudaFuncSetAttribute(cross_mma, cudaFuncAttributeMaxDynamicSharedMemorySize, CROSS_SMEM);
    cudaFuncSetAttribute(aw_mma,    cudaFuncAttributeMaxDynamicSharedMemorySize, AW_SMEM);

    pack_fsq <<<dim3(B_ * SEQ / 8, 2), 256>>>(F0r, F1r, m0, m1);
    pack_w   <<<dim3(16, 8, 2), dim3(32, 32)>>>(W0, W1);
    cross_mma<<<dim3(2, 2, B_), 256, CROSS_SMEM>>>();
    aw_mma   <<<dim3(8, 2, B_ * 2), 256, AW_SMEM>>>();
    conv_kernel<<<dim3(SEQ / 32, B_, 2), 256>>>(conv_w, conv_b, out);
}